// round 1
// baseline (speedup 1.0000x reference)
#include <cuda_runtime.h>
#include <cstdint>

#define NA 128        // atoms per molecule
#define FDIM 512      // feature dim
#define HID 128       // hidden dim
#define KC 128        // K chunk
#define NCHUNK (FDIM / KC)
#define SH_STRIDE 132 // padded row stride for h tile (floats)
#define SW_STRIDE 136 // padded row stride for W1 tile (floats)
#define THREADS 256

__device__ __forceinline__ float to_tf32(float x) {
    float r;
    asm("cvt.rna.tf32.f32 %0, %1;" : "=f"(r) : "f"(x));
    return r;
}

__global__ void __launch_bounds__(THREADS, 1)
atom_pool_kernel(const float* __restrict__ h,
                 const float* __restrict__ W1,
                 const float* __restrict__ b1,
                 const float* __restrict__ W2,
                 const float* __restrict__ b2,
                 float* __restrict__ out) {
    extern __shared__ float smem[];
    float* sH    = smem;                      // [NA][SH_STRIDE]
    float* sW    = sH + NA * SH_STRIDE;       // [KC][SW_STRIDE]
    float* sB1   = sW + KC * SW_STRIDE;       // [HID]
    float* sW2   = sB1 + HID;                 // [HID]
    float* sGate = sW2 + HID;                 // [NA]

    const int m    = blockIdx.x;
    const int tid  = threadIdx.x;
    const int warp = tid >> 5;
    const int lane = tid & 31;
    const int g    = lane >> 2;  // groupID (0..7)
    const int tg   = lane & 3;   // thread-in-group (0..3)

    if (tid < HID) { sB1[tid] = b1[tid]; sW2[tid] = W2[tid]; }

    const float* hm = h + (size_t)m * NA * FDIM;

    // Accumulators: warp owns rows [16*warp, 16*warp+16) x all 128 hid cols
    // 16 n-tiles of m16n8, 4 f32 regs each.
    float c[16][4];
#pragma unroll
    for (int ti = 0; ti < 16; ti++)
#pragma unroll
        for (int j = 0; j < 4; j++) c[ti][j] = 0.f;

    for (int ch = 0; ch < NCHUNK; ch++) {
        __syncthreads();  // protect previous iteration's smem reads

        // --- load h chunk [NA x KC] into sH (tf32-rounded), coalesced float4 ---
#pragma unroll
        for (int i = 0; i < 16; i++) {
            int idx = tid + i * THREADS;     // 0..4095 float4 slots
            int row = idx >> 5;              // 32 float4 per 128-float row
            int c4  = idx & 31;
            float4 v = *(const float4*)(hm + (size_t)row * FDIM + ch * KC + c4 * 4);
            float* dst = sH + row * SH_STRIDE + c4 * 4;
            dst[0] = to_tf32(v.x); dst[1] = to_tf32(v.y);
            dst[2] = to_tf32(v.z); dst[3] = to_tf32(v.w);
        }
        // --- load W1 chunk [KC x HID] into sW (tf32-rounded) ---
#pragma unroll
        for (int i = 0; i < 16; i++) {
            int idx = tid + i * THREADS;
            int row = idx >> 5;
            int c4  = idx & 31;
            float4 v = *(const float4*)(W1 + (size_t)(ch * KC + row) * HID + c4 * 4);
            float* dst = sW + row * SW_STRIDE + c4 * 4;
            dst[0] = to_tf32(v.x); dst[1] = to_tf32(v.y);
            dst[2] = to_tf32(v.z); dst[3] = to_tf32(v.w);
        }
        __syncthreads();

        const int R = warp * 16;
#pragma unroll
        for (int k8 = 0; k8 < KC / 8; k8++) {
            const int k0 = k8 * 8;
            // A fragment (m16k8, tf32): conflict-free (132 % 32 == 4)
            uint32_t a0 = __float_as_uint(sH[(R + g)     * SH_STRIDE + k0 + tg]);
            uint32_t a1 = __float_as_uint(sH[(R + g + 8) * SH_STRIDE + k0 + tg]);
            uint32_t a2 = __float_as_uint(sH[(R + g)     * SH_STRIDE + k0 + tg + 4]);
            uint32_t a3 = __float_as_uint(sH[(R + g + 8) * SH_STRIDE + k0 + tg + 4]);
#pragma unroll
            for (int ti = 0; ti < 16; ti++) {
                // B fragment (k8n8): conflict-free (136 % 32 == 8)
                uint32_t b0r = __float_as_uint(sW[(k0 + tg)     * SW_STRIDE + ti * 8 + g]);
                uint32_t b1r = __float_as_uint(sW[(k0 + tg + 4) * SW_STRIDE + ti * 8 + g]);
                asm volatile(
                    "mma.sync.aligned.m16n8k8.row.col.f32.tf32.tf32.f32 "
                    "{%0,%1,%2,%3}, {%4,%5,%6,%7}, {%8,%9}, {%0,%1,%2,%3};\n"
                    : "+f"(c[ti][0]), "+f"(c[ti][1]), "+f"(c[ti][2]), "+f"(c[ti][3])
                    : "r"(a0), "r"(a1), "r"(a2), "r"(a3), "r"(b0r), "r"(b1r));
            }
        }
    }

    // --- epilogue: A += b1, relu, dot W2, reduce across quad, sigmoid ---
    float zlo = 0.f, zhi = 0.f;
#pragma unroll
    for (int ti = 0; ti < 16; ti++) {
        int col0 = ti * 8 + 2 * tg;
        int col1 = col0 + 1;
        float w20 = sW2[col0], w21 = sW2[col1];
        float b10 = sB1[col0], b11 = sB1[col1];
        zlo += fmaxf(c[ti][0] + b10, 0.f) * w20 + fmaxf(c[ti][1] + b11, 0.f) * w21;
        zhi += fmaxf(c[ti][2] + b10, 0.f) * w20 + fmaxf(c[ti][3] + b11, 0.f) * w21;
    }
    zlo += __shfl_xor_sync(0xffffffffu, zlo, 1);
    zlo += __shfl_xor_sync(0xffffffffu, zlo, 2);
    zhi += __shfl_xor_sync(0xffffffffu, zhi, 1);
    zhi += __shfl_xor_sync(0xffffffffu, zhi, 2);
    if (tg == 0) {
        float bb  = b2[0];
        int   row = warp * 16 + g;
        sGate[row]     = 1.f / (1.f + expf(-(zlo + bb)));
        sGate[row + 8] = 1.f / (1.f + expf(-(zhi + bb)));
    }
    __syncthreads();

    // --- phase 2: out[m,f] = sum_n gate[n] * h[m,n,f]  (h re-read hits L2) ---
    float acc0 = 0.f, acc1 = 0.f;
    const int f = tid;  // 0..255, covers f and f+256
#pragma unroll 8
    for (int n = 0; n < NA; n++) {
        float wv = sGate[n];
        acc0 = fmaf(wv, hm[(size_t)n * FDIM + f],       acc0);
        acc1 = fmaf(wv, hm[(size_t)n * FDIM + f + 256], acc1);
    }
    out[(size_t)m * FDIM + f]       = acc0;
    out[(size_t)m * FDIM + f + 256] = acc1;
}

extern "C" void kernel_launch(void* const* d_in, const int* in_sizes, int n_in,
                              void* d_out, int out_size) {
    const float* h  = (const float*)d_in[0];
    const float* W1 = (const float*)d_in[1];
    const float* b1 = (const float*)d_in[2];
    const float* W2 = (const float*)d_in[3];
    const float* b2 = (const float*)d_in[4];
    float* out = (float*)d_out;

    int M = in_sizes[0] / (NA * FDIM);  // molecules
    size_t smem = (size_t)(NA * SH_STRIDE + KC * SW_STRIDE + 3 * HID) * sizeof(float);
    cudaFuncSetAttribute(atom_pool_kernel,
                         cudaFuncAttributeMaxDynamicSharedMemorySize, (int)smem);
    atom_pool_kernel<<<M, THREADS, smem>>>(h, W1, b1, W2, b2, out);
}

// round 3
// speedup vs baseline: 1.3252x; 1.3252x over previous
#include <cuda_runtime.h>
#include <cstdint>

#define ATOMS   128
#define FDIM    512
#define HID     128
#define KC      32            // K per pipeline stage
#define NCH     (FDIM / KC)   // 16
#define THREADS 256

#define SH_STRIDE 36          // floats per A row (32 data + 4 pad); 144 B (16B-mult)
#define SW_STRIDE 136         // floats per B row (128 data + 8 pad); 544 B

// float offsets in smem
#define SH0 0
#define SH1 (SH0 + ATOMS * SH_STRIDE)        // 4608
#define SW0 (SH1 + ATOMS * SH_STRIDE)        // 9216
#define SW1 (SW0 + KC * SW_STRIDE)           // 13568
#define B1F (SW1 + KC * SW_STRIDE)           // 17920
#define W2F (B1F + HID)                      // 18048
#define ZPF (W2F + HID)                      // 18176  (2 x 128 partial z)
#define GTF (ZPF + 2 * ATOMS)                // 18432  (gates)
#define SMEM_FLOATS (GTF + ATOMS)            // 18560
#define SMEM_BYTES  (SMEM_FLOATS * 4)        // 74240

// W1 pre-rounded to tf32 (RNA), same [FDIM][HID] layout
__device__ float g_W1t[FDIM * HID];

__device__ __forceinline__ float to_tf32(float x) {
    float r;
    asm("cvt.rna.tf32.f32 %0, %1;" : "=f"(r) : "f"(x));
    return r;
}

__global__ void format_w1_kernel(const float* __restrict__ W1) {
    int idx = blockIdx.x * blockDim.x + threadIdx.x;
    g_W1t[idx] = to_tf32(W1[idx]);
}

__device__ __forceinline__ uint32_t smem_u32(const void* p) {
    uint32_t a;
    asm("{ .reg .u64 t; cvta.to.shared.u64 t, %1; cvt.u32.u64 %0, t; }" : "=r"(a) : "l"(p));
    return a;
}

__device__ __forceinline__ void cp_async16(uint32_t dst, const void* src) {
    asm volatile("cp.async.cg.shared.global [%0], [%1], 16;\n"
                 :: "r"(dst), "l"(src) : "memory");
}

__global__ void __launch_bounds__(THREADS, 2)
atom_pool_kernel(const float* __restrict__ h,
                 const float* __restrict__ b1,
                 const float* __restrict__ W2,
                 const float* __restrict__ b2,
                 float* __restrict__ out) {
    extern __shared__ float smem[];
    const uint32_t sbase = smem_u32(smem);

    const int m    = blockIdx.x;
    const int tid  = threadIdx.x;
    const int wid  = tid >> 5;
    const int lane = tid & 31;
    const int g    = lane >> 2;   // 0..7
    const int tg   = lane & 3;    // 0..3

    const float* hm = h + (size_t)m * ATOMS * FDIM;

    if (tid < HID) { smem[B1F + tid] = b1[tid]; smem[W2F + tid] = W2[tid]; }

    // warp tile: rows [R, R+32), cols [C, C+64)
    const int R = (wid & 3) * 32;
    const int C = (wid >> 2) * 64;

    float c[2][8][4];
#pragma unroll
    for (int mt = 0; mt < 2; mt++)
#pragma unroll
        for (int ti = 0; ti < 8; ti++)
#pragma unroll
            for (int j = 0; j < 4; j++) c[mt][ti][j] = 0.f;

    // precomputed cp.async indices
    const int arow = tid >> 3, af4 = tid & 7;     // A: 4 iters of (row += 32)
    const int brow = tid >> 5, bf4 = tid & 31;    // B: 4 iters of (row += 8)

    // ---- prefetch lambda-ish macro ----
#define PREFETCH(ch)                                                              \
    do {                                                                          \
        int _s = (ch) & 1;                                                        \
        uint32_t _dA = sbase + (_s ? SH1 : SH0) * 4;                              \
        uint32_t _dB = sbase + (_s ? SW1 : SW0) * 4;                              \
        const float* _gA = hm + (ch) * KC;                                        \
        const float* _gB = g_W1t + (size_t)(ch) * KC * HID;                       \
        _Pragma("unroll")                                                         \
        for (int j = 0; j < 4; j++) {                                             \
            int r = arow + j * 32;                                                \
            cp_async16(_dA + (r * SH_STRIDE + af4 * 4) * 4,                       \
                       _gA + (size_t)r * FDIM + af4 * 4);                         \
        }                                                                         \
        _Pragma("unroll")                                                         \
        for (int j = 0; j < 4; j++) {                                             \
            int r = brow + j * 8;                                                 \
            cp_async16(_dB + (r * SW_STRIDE + bf4 * 4) * 4,                       \
                       _gB + (size_t)r * HID + bf4 * 4);                          \
        }                                                                         \
        asm volatile("cp.async.commit_group;\n" ::: "memory");                    \
    } while (0)

    PREFETCH(0);

#pragma unroll 1
    for (int ch = 0; ch < NCH; ch++) {
        if (ch + 1 < NCH) {
            PREFETCH(ch + 1);
            asm volatile("cp.async.wait_group 1;\n" ::: "memory");
        } else {
            asm volatile("cp.async.wait_group 0;\n" ::: "memory");
        }
        __syncthreads();

        const float* sh = smem + ((ch & 1) ? SH1 : SH0);
        const float* sw = smem + ((ch & 1) ? SW1 : SW0);

#pragma unroll
        for (int k8 = 0; k8 < KC / 8; k8++) {
            const int k0 = k8 * 8;
            uint32_t a[2][4];
#pragma unroll
            for (int mt = 0; mt < 2; mt++) {
                const int Rm = R + mt * 16;
                a[mt][0] = __float_as_uint(sh[(Rm + g)     * SH_STRIDE + k0 + tg]);
                a[mt][1] = __float_as_uint(sh[(Rm + g + 8) * SH_STRIDE + k0 + tg]);
                a[mt][2] = __float_as_uint(sh[(Rm + g)     * SH_STRIDE + k0 + tg + 4]);
                a[mt][3] = __float_as_uint(sh[(Rm + g + 8) * SH_STRIDE + k0 + tg + 4]);
            }
#pragma unroll
            for (int ti = 0; ti < 8; ti++) {
                const int col = C + ti * 8 + g;
                uint32_t b0 = __float_as_uint(sw[(k0 + tg)     * SW_STRIDE + col]);
                uint32_t b1r = __float_as_uint(sw[(k0 + tg + 4) * SW_STRIDE + col]);
#pragma unroll
                for (int mt = 0; mt < 2; mt++) {
                    asm volatile(
                        "mma.sync.aligned.m16n8k8.row.col.f32.tf32.tf32.f32 "
                        "{%0,%1,%2,%3}, {%4,%5,%6,%7}, {%8,%9}, {%0,%1,%2,%3};\n"
                        : "+f"(c[mt][ti][0]), "+f"(c[mt][ti][1]),
                          "+f"(c[mt][ti][2]), "+f"(c[mt][ti][3])
                        : "r"(a[mt][0]), "r"(a[mt][1]), "r"(a[mt][2]), "r"(a[mt][3]),
                          "r"(b0), "r"(b1r));
                }
            }
        }
        __syncthreads();
    }

    // ---- epilogue: partial z over this warp's 64 cols ----
    const float* sB1 = smem + B1F;
    const float* sW2 = smem + W2F;
    float zlo[2] = {0.f, 0.f}, zhi[2] = {0.f, 0.f};
#pragma unroll
    for (int mt = 0; mt < 2; mt++) {
#pragma unroll
        for (int ti = 0; ti < 8; ti++) {
            int col0 = C + ti * 8 + 2 * tg;
            int col1 = col0 + 1;
            float w20 = sW2[col0], w21 = sW2[col1];
            float b10 = sB1[col0], b11 = sB1[col1];
            zlo[mt] += fmaxf(c[mt][ti][0] + b10, 0.f) * w20
                     + fmaxf(c[mt][ti][1] + b11, 0.f) * w21;
            zhi[mt] += fmaxf(c[mt][ti][2] + b10, 0.f) * w20
                     + fmaxf(c[mt][ti][3] + b11, 0.f) * w21;
        }
    }
#pragma unroll
    for (int mt = 0; mt < 2; mt++) {
        zlo[mt] += __shfl_xor_sync(0xffffffffu, zlo[mt], 1);
        zlo[mt] += __shfl_xor_sync(0xffffffffu, zlo[mt], 2);
        zhi[mt] += __shfl_xor_sync(0xffffffffu, zhi[mt], 1);
        zhi[mt] += __shfl_xor_sync(0xffffffffu, zhi[mt], 2);
    }
    const int half = wid >> 2;  // col half
    if (tg == 0) {
        smem[ZPF + half * ATOMS + R + g]      = zlo[0];
        smem[ZPF + half * ATOMS + R + g + 8]  = zhi[0];
        smem[ZPF + half * ATOMS + R + g + 16] = zlo[1];
        smem[ZPF + half * ATOMS + R + g + 24] = zhi[1];
    }
    __syncthreads();

    if (tid < ATOMS) {
        float z = smem[ZPF + tid] + smem[ZPF + ATOMS + tid] + b2[0];
        smem[GTF + tid] = 1.f / (1.f + expf(-z));
    }
    __syncthreads();

    // ---- phase 2: out[m,f] = sum_n gate[n] * h[m,n,f] (L2 re-read) ----
    float acc0 = 0.f, acc1 = 0.f;
    const int f = tid;
#pragma unroll 8
    for (int n = 0; n < ATOMS; n++) {
        float wv = smem[GTF + n];
        acc0 = fmaf(wv, hm[(size_t)n * FDIM + f],       acc0);
        acc1 = fmaf(wv, hm[(size_t)n * FDIM + f + 256], acc1);
    }
    out[(size_t)m * FDIM + f]       = acc0;
    out[(size_t)m * FDIM + f + 256] = acc1;
#undef PREFETCH
}

extern "C" void kernel_launch(void* const* d_in, const int* in_sizes, int n_in,
                              void* d_out, int out_size) {
    const float* h  = (const float*)d_in[0];
    const float* W1 = (const float*)d_in[1];
    const float* b1 = (const float*)d_in[2];
    const float* W2 = (const float*)d_in[3];
    const float* b2 = (const float*)d_in[4];
    float* out = (float*)d_out;

    int M = in_sizes[0] / (ATOMS * FDIM);

    format_w1_kernel<<<(FDIM * HID) / 256, 256>>>(W1);

    cudaFuncSetAttribute(atom_pool_kernel,
                         cudaFuncAttributeMaxDynamicSharedMemorySize, SMEM_BYTES);
    atom_pool_kernel<<<M, THREADS, SMEM_BYTES>>>(h, b1, W2, b2, out);
}

// round 5
// speedup vs baseline: 1.8880x; 1.4248x over previous
#include <cuda_runtime.h>
#include <cuda_fp16.h>
#include <cstdint>

#define ATOMS   128
#define FDIM    512
#define HID     128
#define KC      64
#define NCH     (FDIM / KC)   // 8
#define THREADS 256

#define LDA 72    // halves per A row (64 + 8 pad)
#define LDB 136   // halves per B row (128 + 8 pad)

// byte offsets in smem
#define SA0 0
#define SA1 (SA0 + ATOMS * LDA * 2)     // 18432
#define SB0 (SA1 + ATOMS * LDA * 2)     // 36864
#define SB1 (SB0 + KC * LDB * 2)        // 54272
#define B1F (SB1 + KC * LDB * 2)        // 71680 (128 f32)
#define W2F (B1F + 512)                 // 72192 (128 f32)
#define ZPF (W2F + 512)                 // 72704 (256 f32)
#define GTF (ZPF + 1024)                // 73728 (128 f32)
#define SMEM_BYTES (GTF + 512)          // 74240

__device__ __half g_W1h[FDIM * HID];    // W1 pre-converted to fp16, [k][n]

__global__ void format_w1_kernel(const float* __restrict__ W1) {
    int idx = blockIdx.x * blockDim.x + threadIdx.x;
    g_W1h[idx] = __float2half_rn(W1[idx]);
}

__device__ __forceinline__ uint32_t smem_u32(const void* p) {
    uint32_t a;
    asm("{ .reg .u64 t; cvta.to.shared.u64 t, %1; cvt.u32.u64 %0, t; }" : "=r"(a) : "l"(p));
    return a;
}

__device__ __forceinline__ uint32_t h2_bits(__half2 v) {
    uint32_t u;
    __builtin_memcpy(&u, &v, 4);
    return u;
}

__device__ __forceinline__ void cp_async16(uint32_t dst, const void* src) {
    asm volatile("cp.async.cg.shared.global [%0], [%1], 16;\n" :: "r"(dst), "l"(src) : "memory");
}

__device__ __forceinline__ void ldsm_x4(uint32_t (&r)[4], uint32_t addr) {
    asm volatile("ldmatrix.sync.aligned.m8n8.x4.shared.b16 {%0,%1,%2,%3}, [%4];"
                 : "=r"(r[0]), "=r"(r[1]), "=r"(r[2]), "=r"(r[3]) : "r"(addr));
}
__device__ __forceinline__ void ldsm_x4t(uint32_t (&r)[4], uint32_t addr) {
    asm volatile("ldmatrix.sync.aligned.m8n8.x4.trans.shared.b16 {%0,%1,%2,%3}, [%4];"
                 : "=r"(r[0]), "=r"(r[1]), "=r"(r[2]), "=r"(r[3]) : "r"(addr));
}
__device__ __forceinline__ void mma16816(float (&d)[4], const uint32_t (&a)[4],
                                         uint32_t b0, uint32_t b1) {
    asm volatile(
        "mma.sync.aligned.m16n8k16.row.col.f32.f16.f16.f32 "
        "{%0,%1,%2,%3}, {%4,%5,%6,%7}, {%8,%9}, {%0,%1,%2,%3};\n"
        : "+f"(d[0]), "+f"(d[1]), "+f"(d[2]), "+f"(d[3])
        : "r"(a[0]), "r"(a[1]), "r"(a[2]), "r"(a[3]), "r"(b0), "r"(b1));
}

__global__ void __launch_bounds__(THREADS, 2)
atom_pool_kernel(const float* __restrict__ h,
                 const float* __restrict__ b1,
                 const float* __restrict__ W2,
                 const float* __restrict__ b2,
                 float* __restrict__ out) {
    extern __shared__ char smem[];
    const uint32_t sbase = smem_u32(smem);
    float* smf = (float*)smem;

    const int m    = blockIdx.x;
    const int tid  = threadIdx.x;
    const int wid  = tid >> 5;
    const int lane = tid & 31;
    const int g    = lane >> 2;
    const int tg   = lane & 3;

    const float* hm = h + (size_t)m * ATOMS * FDIM;

    if (tid < HID) { smf[B1F / 4 + tid] = b1[tid]; smf[W2F / 4 + tid] = W2[tid]; }

    // warp tile: rows [R, R+32), cols [C, C+64)
    const int R = (wid & 3) * 32;
    const int C = (wid >> 2) * 64;

    float c[2][8][4];
#pragma unroll
    for (int mt = 0; mt < 2; mt++)
#pragma unroll
        for (int ti = 0; ti < 8; ti++)
#pragma unroll
            for (int j = 0; j < 4; j++) c[mt][ti][j] = 0.f;

#define CPB(ch)                                                                    \
    do {                                                                           \
        uint32_t _dB = sbase + (((ch) & 1) ? SB1 : SB0);                           \
        const __half* _gB = g_W1h + (size_t)(ch) * KC * HID;                       \
        _Pragma("unroll")                                                          \
        for (int j = 0; j < 4; j++) {                                              \
            int idx = j * THREADS + tid;                                           \
            int r = idx >> 4, s = idx & 15;                                        \
            cp_async16(_dB + (r * LDB + s * 8) * 2, _gB + (size_t)r * HID + s * 8);\
        }                                                                          \
        asm volatile("cp.async.commit_group;\n" ::: "memory");                     \
    } while (0)

#define LDGA(ch, pa0, pa1)                                                         \
    do {                                                                           \
        const float* _gA = hm + (ch) * KC;                                         \
        _Pragma("unroll")                                                          \
        for (int j = 0; j < 4; j++) {                                              \
            int idx = j * THREADS + tid;                                           \
            int r = idx >> 3, s = idx & 7;                                         \
            const float* _p = _gA + (size_t)r * FDIM + s * 8;                      \
            pa0[j] = *(const float4*)_p;                                           \
            pa1[j] = *(const float4*)(_p + 4);                                     \
        }                                                                          \
    } while (0)

#define STSA(ch, pa0, pa1)                                                         \
    do {                                                                           \
        uint32_t _dA = sbase + (((ch) & 1) ? SA1 : SA0);                           \
        _Pragma("unroll")                                                          \
        for (int j = 0; j < 4; j++) {                                              \
            int idx = j * THREADS + tid;                                           \
            int r = idx >> 3, s = idx & 7;                                         \
            uint32_t v0 = h2_bits(__floats2half2_rn(pa0[j].x, pa0[j].y));          \
            uint32_t v1 = h2_bits(__floats2half2_rn(pa0[j].z, pa0[j].w));          \
            uint32_t v2 = h2_bits(__floats2half2_rn(pa1[j].x, pa1[j].y));          \
            uint32_t v3 = h2_bits(__floats2half2_rn(pa1[j].z, pa1[j].w));          \
            uint32_t a = _dA + (r * LDA + s * 8) * 2;                              \
            asm volatile("st.shared.v4.b32 [%0], {%1,%2,%3,%4};"                   \
                         :: "r"(a), "r"(v0), "r"(v1), "r"(v2), "r"(v3)             \
                         : "memory");                                              \
        }                                                                          \
    } while (0)

    float4 pa0[4], pa1[4];

    // prologue: stage chunk 0
    CPB(0);
    LDGA(0, pa0, pa1);
    STSA(0, pa0, pa1);
    asm volatile("cp.async.wait_group 0;\n" ::: "memory");
    __syncthreads();

#pragma unroll 1
    for (int ch = 0; ch < NCH; ch++) {
        const uint32_t sa = sbase + ((ch & 1) ? SA1 : SA0);
        const uint32_t sb = sbase + ((ch & 1) ? SB1 : SB0);

        if (ch + 1 < NCH) {
            CPB(ch + 1);
            LDGA(ch + 1, pa0, pa1);
        }

        // lane-mapped ldmatrix base offsets
        const int la_row = lane & 15, la_k = (lane >> 4) << 3;

#pragma unroll
        for (int k16 = 0; k16 < KC / 16; k16++) {
            const int k0 = k16 * 16;
            uint32_t a[2][4];
#pragma unroll
            for (int mt = 0; mt < 2; mt++)
                ldsm_x4(a[mt], sa + ((R + mt * 16 + la_row) * LDA + k0 + la_k) * 2);
#pragma unroll
            for (int tp = 0; tp < 4; tp++) {
                uint32_t b[4];
                ldsm_x4t(b, sb + ((k0 + la_row) * LDB + C + tp * 16 + la_k) * 2);
#pragma unroll
                for (int mt = 0; mt < 2; mt++) {
                    mma16816(c[mt][tp * 2],     a[mt], b[0], b[1]);
                    mma16816(c[mt][tp * 2 + 1], a[mt], b[2], b[3]);
                }
            }
        }

        if (ch + 1 < NCH) {
            asm volatile("cp.async.wait_group 0;\n" ::: "memory");
            __syncthreads();                 // everyone done reading ch tiles
            STSA(ch + 1, pa0, pa1);
            __syncthreads();                 // ch+1 tiles ready
        }
    }

    // ---- epilogue: partial z over this warp's 64 cols ----
    const float* sB1 = smf + B1F / 4;
    const float* sW2 = smf + W2F / 4;
    float zlo[2] = {0.f, 0.f}, zhi[2] = {0.f, 0.f};
#pragma unroll
    for (int mt = 0; mt < 2; mt++) {
#pragma unroll
        for (int ti = 0; ti < 8; ti++) {
            int col0 = C + ti * 8 + 2 * tg;
            float w20 = sW2[col0], w21 = sW2[col0 + 1];
            float b10 = sB1[col0], b11 = sB1[col0 + 1];
            zlo[mt] += fmaxf(c[mt][ti][0] + b10, 0.f) * w20
                     + fmaxf(c[mt][ti][1] + b11, 0.f) * w21;
            zhi[mt] += fmaxf(c[mt][ti][2] + b10, 0.f) * w20
                     + fmaxf(c[mt][ti][3] + b11, 0.f) * w21;
        }
    }
#pragma unroll
    for (int mt = 0; mt < 2; mt++) {
        zlo[mt] += __shfl_xor_sync(0xffffffffu, zlo[mt], 1);
        zlo[mt] += __shfl_xor_sync(0xffffffffu, zlo[mt], 2);
        zhi[mt] += __shfl_xor_sync(0xffffffffu, zhi[mt], 1);
        zhi[mt] += __shfl_xor_sync(0xffffffffu, zhi[mt], 2);
    }
    const int half = wid >> 2;
    if (tg == 0) {
        float* zp = smf + ZPF / 4 + half * ATOMS;
        zp[R + g]      = zlo[0];
        zp[R + g + 8]  = zhi[0];
        zp[R + g + 16] = zlo[1];
        zp[R + g + 24] = zhi[1];
    }
    __syncthreads();

    if (tid < ATOMS) {
        float z = smf[ZPF / 4 + tid] + smf[ZPF / 4 + ATOMS + tid] + b2[0];
        smf[GTF / 4 + tid] = 1.f / (1.f + expf(-z));
    }
    __syncthreads();

    // ---- phase 2: out[m,f] = sum_n gate[n] * h[m,n,f] (f32 h, L2 re-read) ----
    float acc0 = 0.f, acc1 = 0.f;
    const int f = tid;
#pragma unroll 8
    for (int n = 0; n < ATOMS; n++) {
        float wv = smf[GTF / 4 + n];
        acc0 = fmaf(wv, hm[(size_t)n * FDIM + f],       acc0);
        acc1 = fmaf(wv, hm[(size_t)n * FDIM + f + 256], acc1);
    }
    out[(size_t)m * FDIM + f]       = acc0;
    out[(size_t)m * FDIM + f + 256] = acc1;

#undef CPB
#undef LDGA
#undef STSA
}

extern "C" void kernel_launch(void* const* d_in, const int* in_sizes, int n_in,
                              void* d_out, int out_size) {
    const float* h  = (const float*)d_in[0];
    const float* W1 = (const float*)d_in[1];
    const float* b1 = (const float*)d_in[2];
    const float* W2 = (const float*)d_in[3];
    const float* b2 = (const float*)d_in[4];
    float* out = (float*)d_out;

    int M = in_sizes[0] / (ATOMS * FDIM);

    format_w1_kernel<<<(FDIM * HID) / 256, 256>>>(W1);

    cudaFuncSetAttribute(atom_pool_kernel,
                         cudaFuncAttributeMaxDynamicSharedMemorySize, SMEM_BYTES);
    atom_pool_kernel<<<M, THREADS, SMEM_BYTES>>>(h, b1, W2, b2, out);
}

// round 6
// speedup vs baseline: 2.1418x; 1.1344x over previous
#include <cuda_runtime.h>
#include <cuda_fp16.h>
#include <cstdint>

#define ATOMS   128
#define FDIM    512
#define HID     128
#define KC      64
#define NCH     (FDIM / KC)   // 8
#define THREADS 256

#define LDA 72    // halves per A row (64 + 8 pad)
#define LDB 136   // halves per B row (128 + 8 pad)

#define SA_SZ   (ATOMS * LDA * 2)       // 18432
#define SB_SZ   (KC * LDB * 2)          // 17408
#define SA_BASE 0                       // 3 stages
#define SB_BASE (3 * SA_SZ)             // 55296, 2 stages
#define B1F     (SB_BASE + 2 * SB_SZ)   // 90112 (128 f32)
#define W2F     (B1F + 512)             // 90624 (128 f32)
#define ZPF     (W2F + 512)             // 91136 (256 f32)
#define GTF     (ZPF + 1024)            // 92160 (128 f32)
#define SMEM_BYTES (GTF + 512)          // 92672

__device__ __half g_W1h[FDIM * HID];    // W1 fp16, [k][n]

__global__ void format_w1_kernel(const float* __restrict__ W1) {
    int idx = blockIdx.x * blockDim.x + threadIdx.x;
    g_W1h[idx] = __float2half_rn(W1[idx]);
}

__device__ __forceinline__ uint32_t smem_u32(const void* p) {
    uint32_t a;
    asm("{ .reg .u64 t; cvta.to.shared.u64 t, %1; cvt.u32.u64 %0, t; }" : "=r"(a) : "l"(p));
    return a;
}
__device__ __forceinline__ uint32_t h2_bits(__half2 v) {
    uint32_t u; __builtin_memcpy(&u, &v, 4); return u;
}
__device__ __forceinline__ void cp_async16(uint32_t dst, const void* src) {
    asm volatile("cp.async.cg.shared.global [%0], [%1], 16;\n" :: "r"(dst), "l"(src) : "memory");
}
__device__ __forceinline__ void ldsm_x4(uint32_t (&r)[4], uint32_t addr) {
    asm volatile("ldmatrix.sync.aligned.m8n8.x4.shared.b16 {%0,%1,%2,%3}, [%4];"
                 : "=r"(r[0]), "=r"(r[1]), "=r"(r[2]), "=r"(r[3]) : "r"(addr));
}
__device__ __forceinline__ void ldsm_x4t(uint32_t (&r)[4], uint32_t addr) {
    asm volatile("ldmatrix.sync.aligned.m8n8.x4.trans.shared.b16 {%0,%1,%2,%3}, [%4];"
                 : "=r"(r[0]), "=r"(r[1]), "=r"(r[2]), "=r"(r[3]) : "r"(addr));
}
__device__ __forceinline__ void mma16816(float (&d)[4], const uint32_t (&a)[4],
                                         uint32_t b0, uint32_t b1) {
    asm volatile(
        "mma.sync.aligned.m16n8k16.row.col.f32.f16.f16.f32 "
        "{%0,%1,%2,%3}, {%4,%5,%6,%7}, {%8,%9}, {%0,%1,%2,%3};\n"
        : "+f"(d[0]), "+f"(d[1]), "+f"(d[2]), "+f"(d[3])
        : "r"(a[0]), "r"(a[1]), "r"(a[2]), "r"(a[3]), "r"(b0), "r"(b1));
}

__global__ void __launch_bounds__(THREADS, 2)
atom_pool_kernel(const float* __restrict__ h,
                 const float* __restrict__ b1,
                 const float* __restrict__ W2,
                 const float* __restrict__ b2,
                 float* __restrict__ out) {
    extern __shared__ char smem[];
    const uint32_t sbase = smem_u32(smem);
    float* smf = (float*)smem;

    const int m    = blockIdx.x;
    const int tid  = threadIdx.x;
    const int wid  = tid >> 5;
    const int lane = tid & 31;
    const int g    = lane >> 2;
    const int tg   = lane & 3;

    const float* hm = h + (size_t)m * ATOMS * FDIM;

    if (tid < HID) { smf[B1F / 4 + tid] = b1[tid]; smf[W2F / 4 + tid] = W2[tid]; }

    const int R = (wid & 3) * 32;
    const int C = (wid >> 2) * 64;

    float c[2][8][4];
#pragma unroll
    for (int mt = 0; mt < 2; mt++)
#pragma unroll
        for (int ti = 0; ti < 8; ti++)
#pragma unroll
            for (int j = 0; j < 4; j++) c[mt][ti][j] = 0.f;

#define CPB(ch)                                                                    \
    do {                                                                           \
        uint32_t _dB = sbase + SB_BASE + ((ch) & 1) * SB_SZ;                       \
        const __half* _gB = g_W1h + (size_t)(ch) * KC * HID;                       \
        _Pragma("unroll")                                                          \
        for (int j = 0; j < 4; j++) {                                              \
            int idx = j * THREADS + tid;                                           \
            int r = idx >> 4, s = idx & 15;                                        \
            cp_async16(_dB + (r * LDB + s * 8) * 2, _gB + (size_t)r * HID + s * 8);\
        }                                                                          \
        asm volatile("cp.async.commit_group;\n" ::: "memory");                     \
    } while (0)

#define LDGA(ch)                                                                   \
    do {                                                                           \
        const float* _gA = hm + (ch) * KC;                                         \
        _Pragma("unroll")                                                          \
        for (int j = 0; j < 4; j++) {                                              \
            int idx = j * THREADS + tid;                                           \
            int r = idx >> 3, s = idx & 7;                                         \
            const float* _p = _gA + (size_t)r * FDIM + s * 8;                      \
            pa0[j] = *(const float4*)_p;                                           \
            pa1[j] = *(const float4*)(_p + 4);                                     \
        }                                                                          \
    } while (0)

#define STSA(ch)                                                                   \
    do {                                                                           \
        uint32_t _dA = sbase + SA_BASE + ((ch) % 3) * SA_SZ;                       \
        _Pragma("unroll")                                                          \
        for (int j = 0; j < 4; j++) {                                              \
            int idx = j * THREADS + tid;                                           \
            int r = idx >> 3, s = idx & 7;                                         \
            uint32_t v0 = h2_bits(__floats2half2_rn(pa0[j].x, pa0[j].y));          \
            uint32_t v1 = h2_bits(__floats2half2_rn(pa0[j].z, pa0[j].w));          \
            uint32_t v2 = h2_bits(__floats2half2_rn(pa1[j].x, pa1[j].y));          \
            uint32_t v3 = h2_bits(__floats2half2_rn(pa1[j].z, pa1[j].w));          \
            uint32_t a = _dA + (r * LDA + s * 8) * 2;                              \
            asm volatile("st.shared.v4.b32 [%0], {%1,%2,%3,%4};"                   \
                         :: "r"(a), "r"(v0), "r"(v1), "r"(v2), "r"(v3)             \
                         : "memory");                                              \
        }                                                                          \
    } while (0)

    float4 pa0[4], pa1[4];

    // ---- prologue ----
    CPB(0);                                  // B(0) in flight
    LDGA(0); STSA(0);                        // A(0) staged
    LDGA(1);                                 // regs for STSA(1)
    asm volatile("cp.async.wait_group 0;\n" ::: "memory");   // B(0) landed

    // ---- mainloop: ONE barrier per chunk ----
#pragma unroll 1
    for (int ch = 0; ch < NCH; ch++) {
        if (ch + 1 < NCH) STSA(ch + 1);      // pre-barrier: buf (ch+1)%3 free since MMA(ch-2)
        if (ch + 2 < NCH) LDGA(ch + 2);      // refill regs (DRAM latency hidden by MMA(ch))
        __syncthreads();                     // publish A(ch), B(ch)
        if (ch + 1 < NCH) CPB(ch + 1);       // buf (ch+1)%2 free: MMA(ch-1) done (barrier)

        const uint32_t sa = sbase + SA_BASE + (ch % 3) * SA_SZ;
        const uint32_t sb = sbase + SB_BASE + (ch & 1) * SB_SZ;
        const int la_row = lane & 15, la_k = (lane >> 4) << 3;

#pragma unroll
        for (int k16 = 0; k16 < KC / 16; k16++) {
            const int k0 = k16 * 16;
            uint32_t a[2][4];
#pragma unroll
            for (int mt = 0; mt < 2; mt++)
                ldsm_x4(a[mt], sa + ((R + mt * 16 + la_row) * LDA + k0 + la_k) * 2);
#pragma unroll
            for (int tp = 0; tp < 4; tp++) {
                uint32_t b[4];
                ldsm_x4t(b, sb + ((k0 + la_row) * LDB + C + tp * 16 + la_k) * 2);
#pragma unroll
                for (int mt = 0; mt < 2; mt++) {
                    mma16816(c[mt][tp * 2],     a[mt], b[0], b[1]);
                    mma16816(c[mt][tp * 2 + 1], a[mt], b[2], b[3]);
                }
            }
        }
        if (ch + 1 < NCH)
            asm volatile("cp.async.wait_group 0;\n" ::: "memory");  // B(ch+1) landed
    }

    // ---- epilogue: gate z over this warp's 64 cols ----
    const float* sB1 = smf + B1F / 4;
    const float* sW2 = smf + W2F / 4;
    float zlo[2] = {0.f, 0.f}, zhi[2] = {0.f, 0.f};
#pragma unroll
    for (int mt = 0; mt < 2; mt++) {
#pragma unroll
        for (int ti = 0; ti < 8; ti++) {
            int col0 = C + ti * 8 + 2 * tg;
            float w20 = sW2[col0], w21 = sW2[col0 + 1];
            float b10 = sB1[col0], b11 = sB1[col0 + 1];
            zlo[mt] += fmaxf(c[mt][ti][0] + b10, 0.f) * w20
                     + fmaxf(c[mt][ti][1] + b11, 0.f) * w21;
            zhi[mt] += fmaxf(c[mt][ti][2] + b10, 0.f) * w20
                     + fmaxf(c[mt][ti][3] + b11, 0.f) * w21;
        }
    }
#pragma unroll
    for (int mt = 0; mt < 2; mt++) {
        zlo[mt] += __shfl_xor_sync(0xffffffffu, zlo[mt], 1);
        zlo[mt] += __shfl_xor_sync(0xffffffffu, zlo[mt], 2);
        zhi[mt] += __shfl_xor_sync(0xffffffffu, zhi[mt], 1);
        zhi[mt] += __shfl_xor_sync(0xffffffffu, zhi[mt], 2);
    }
    __syncthreads();   // mainloop smem reads done before ZPF writes (ZPF distinct, but keep ordering tight)
    const int half = wid >> 2;
    if (tg == 0) {
        float* zp = smf + ZPF / 4 + half * ATOMS;
        zp[R + g]      = zlo[0];
        zp[R + g + 8]  = zhi[0];
        zp[R + g + 16] = zlo[1];
        zp[R + g + 24] = zhi[1];
    }
    __syncthreads();

    if (tid < ATOMS) {
        float z = smf[ZPF / 4 + tid] + smf[ZPF / 4 + ATOMS + tid] + b2[0];
        smf[GTF / 4 + tid] = 1.f / (1.f + expf(-z));
    }
    __syncthreads();

    // ---- phase 2: out[m,f] = sum_n gate[n] * h[m,n,f] (float4, L2 re-read) ----
    const int ph   = tid >> 7;            // n parity
    const int c4   = tid & 127;           // float4 column index (0..127)
    const float* gate = smf + GTF / 4;
    float4 acc = make_float4(0.f, 0.f, 0.f, 0.f);
#pragma unroll 8
    for (int n = ph; n < ATOMS; n += 2) {
        float wv = gate[n];
        float4 v = *(const float4*)(hm + (size_t)n * FDIM + c4 * 4);
        acc.x = fmaf(wv, v.x, acc.x);
        acc.y = fmaf(wv, v.y, acc.y);
        acc.z = fmaf(wv, v.z, acc.z);
        acc.w = fmaf(wv, v.w, acc.w);
    }
    // combine parities via smem (reuse SA region — GEMM done)
    float4* red = (float4*)smem;
    if (ph == 1) red[c4] = acc;
    __syncthreads();
    if (ph == 0) {
        float4 o = red[c4];
        acc.x += o.x; acc.y += o.y; acc.z += o.z; acc.w += o.w;
        *(float4*)(out + (size_t)m * FDIM + c4 * 4) = acc;
    }

#undef CPB
#undef LDGA
#undef STSA
}

extern "C" void kernel_launch(void* const* d_in, const int* in_sizes, int n_in,
                              void* d_out, int out_size) {
    const float* h  = (const float*)d_in[0];
    const float* W1 = (const float*)d_in[1];
    const float* b1 = (const float*)d_in[2];
    const float* W2 = (const float*)d_in[3];
    const float* b2 = (const float*)d_in[4];
    float* out = (float*)d_out;

    int M = in_sizes[0] / (ATOMS * FDIM);

    format_w1_kernel<<<(FDIM * HID) / 256, 256>>>(W1);

    cudaFuncSetAttribute(atom_pool_kernel,
                         cudaFuncAttributeMaxDynamicSharedMemorySize, SMEM_BYTES);
    atom_pool_kernel<<<M, THREADS, SMEM_BYTES>>>(h, b1, W2, b2, out);
}